// round 10
// baseline (speedup 1.0000x reference)
#include <cuda_runtime.h>
#include <cstdint>

#define SQRT2F     1.4142135623730951f
#define INVSQRT2F  0.7071067811865476f

using u32 = uint32_t; using u64 = uint64_t; using ull = unsigned long long;

// ======================= helpers =======================
__device__ __forceinline__ ull pack2(float lo, float hi) {
    ull r; asm("mov.b64 %0, {%1, %2};" : "=l"(r) : "f"(lo), "f"(hi)); return r;
}
__device__ __forceinline__ void unpack2(ull v, float& lo, float& hi) {
    asm("mov.b64 {%0, %1}, %2;" : "=f"(lo), "=f"(hi) : "l"(v));
}
__device__ __forceinline__ void fma2(ull& d, ull a, ull b) {
    asm("fma.rn.f32x2 %0, %1, %2, %0;" : "+l"(d) : "l"(a), "l"(b));
}
__device__ __forceinline__ u32 f2tf32(float f) {
    u32 r; asm("cvt.rna.tf32.f32 %0, %1;" : "=r"(r) : "f"(f)); return r;
}
__device__ __forceinline__ u32 smem_u32(const void* p) {
    u32 a; asm("{ .reg .u64 t; cvta.to.shared.u64 t, %1; cvt.u32.u64 %0, t; }" : "=r"(a) : "l"(p));
    return a;
}
__device__ __forceinline__ void cp16(u32 dst, const void* src) {
    asm volatile("cp.async.ca.shared.global [%0], [%1], 16;" :: "r"(dst), "l"(src));
}
#define CP_COMMIT() asm volatile("cp.async.commit_group;" ::: "memory")
#define CP_WAIT(N)  asm volatile("cp.async.wait_group %0;" :: "n"(N) : "memory")

__device__ __forceinline__ void mma_tf32(float* c, const u32* a, const u32* b) {
    asm volatile("mma.sync.aligned.m16n8k8.row.col.f32.tf32.tf32.f32 "
                 "{%0,%1,%2,%3}, {%4,%5,%6,%7}, {%8,%9}, {%0,%1,%2,%3};"
                 : "+f"(c[0]), "+f"(c[1]), "+f"(c[2]), "+f"(c[3])
                 : "r"(a[0]), "r"(a[1]), "r"(a[2]), "r"(a[3]),
                   "r"(b[0]), "r"(b[1]));
}

// ======================= scratch =======================
__device__ __align__(16) float g_p1[8 * 256 * 66 * 66];        // padded conv1 input, tf32-rounded
__device__ __align__(16) float g_out1[8 * 256 * 64 * 64];      // conv1 output (after lrelu, fp32)
__device__ __align__(16) float g_up_pad[8 * 256 * 130 * 130];  // padded upsampled, tf32-rounded
__device__ __align__(16) float g_s64[8 * 128 * 64 * 64];       // 1x1 skip conv at 64x64 (fp32)
__device__ __align__(16) u32   g_wB1[72 * 32 * 256];           // conv1 wts tf32 [chunk][k=32][co=256]
__device__ __align__(16) u32   g_wB2[72 * 32 * 128];           // conv2 wts tf32 [chunk][k=32][co=128]
__device__ __align__(16) float g_wskT[256 * 128];              // skip weights [ci][co], scaled

// ======================= weight prep =======================
__global__ void k_wt1(const float* __restrict__ w) {
    int idx = blockIdx.x * 256 + threadIdx.x;        // 72*32*256 = 589824
    if (idx >= 589824) return;
    int co    = idx & 255;
    int k_l   = (idx >> 8) & 31;
    int chunk = idx >> 13;                            // 0..71
    int koff = chunk >> 3, cic = chunk & 7;
    int ci = cic * 32 + k_l;
    g_wB1[idx] = f2tf32(w[(co * 256 + ci) * 9 + koff] * (1.0f / 48.0f));
}
__global__ void k_wt2(const float* __restrict__ w) {
    int idx = blockIdx.x * 256 + threadIdx.x;        // 72*32*128 = 294912
    if (idx >= 294912) return;
    int co_l = idx & 127;
    int k_l  = (idx >> 7) & 31;
    int i    = idx >> 12;                             // 0..71
    int koff = i >> 3, cic = i & 7;
    int ci = cic * 32 + k_l;
    g_wB2[idx] = f2tf32(w[(co_l * 256 + ci) * 9 + koff] * (1.0f / 48.0f));
}
__global__ void k_wts(const float* __restrict__ w) {
    int idx = blockIdx.x * 256 + threadIdx.x;
    if (idx >= 256 * 128) return;
    int co = idx & 127; int ci = idx >> 7;
    g_wskT[idx] = w[co * 256 + ci] * (1.0f / 16.0f);
}

// ======================= pad x into g_p1 (tf32-rounded) =======================
__global__ void k_pad1(const float* __restrict__ x) {
    int idx = blockIdx.x * 256 + threadIdx.x;        // 8*256*64*64
    int c = idx & 63, r = (idx >> 6) & 63, nc = idx >> 12;
    g_p1[(size_t)nc * 4356 + (r + 1) * 66 + (c + 1)] = __uint_as_float(f2tf32(x[idx]));
}

// ======================= mma.sync tf32 implicit-GEMM conv (3x3, pad 1) =================
// 64x64 warp tiles (acc 128 f32/thread). 8 warps per 256-thread block.
// CONV=1: block M=128 (2 rows x 64) x N=256, in=g_p1, out g_out1.          grid (32,1,8)
// CONV=2: block M=256 (2 rows x 128) x N=128, in=g_up_pad, out d_out+skip. grid (64,1,8)
// A: LDG reg-prefetch 1 iter ahead + STS, 2 stages. B: cp16, 3-stage ring, 2 ahead.
template <int CONV>
__global__ void __launch_bounds__(256, 1) k_conv_mma(const float* __restrict__ bias,
                                                     float* __restrict__ dout) {
    constexpr int PW   = (CONV == 1) ? 66 : 130;
    constexpr int PSZ  = PW * PW;
    constexpr int OW   = (CONV == 1) ? 64 : 128;
    constexpr int BM   = (CONV == 1) ? 128 : 256;
    constexpr int BN   = (CONV == 1) ? 256 : 128;
    constexpr int NWM  = BM / 64;                    // m-warps: 2 or 4
    constexpr int SAP  = BM + 8;                     // A row stride (u32)
    constexpr int SBP  = BN + 8;                     // B row stride (u32)
    constexpr int ASZ  = 32 * SAP;
    constexpr int BSZ  = 32 * SBP;
    constexpr int NLDA = (CONV == 1) ? 16 : 32;      // A LDGs per thread per chunk
    constexpr int BCHK = 32 * BN / 4;                // 16B chunks per B tile
    constexpr int BPT  = BCHK / 256;                 // per thread

    extern __shared__ __align__(16) u32 dynsmem[];
    const u32 sbase = smem_u32(dynsmem);

    const int tile = blockIdx.x;
    const int n    = blockIdx.z;
    const int tid  = threadIdx.x;
    const int wid  = tid >> 5;
    const int lane = tid & 31;
    const int wm   = wid % NWM;
    const int wn   = wid / NWM;
    const int lg   = lane >> 2;          // 0..7
    const int lt   = lane & 3;           // 0..3
    const int pxb  = wm * 64;
    const int cob  = wn * 64;

    const float* in = (CONV == 1) ? g_p1 : g_up_pad;
    const u32* wB = (CONV == 1) ? g_wB1 : g_wB2;

    const int r0 = tile * 2;                         // both convs: 2 rows per tile

    // A-load mapping
    const int apx = (CONV == 1) ? (tid & 127) : tid;           // px in tile
    const int arow = apx / OW, acol = apx % OW;
    const int ak0  = (CONV == 1) ? (tid >> 7) : 0;             // starting k row
    const float* a_base = in + ((size_t)(n * 256 + ak0)) * PSZ
                             + (size_t)(r0 + arow) * PW + acol;

    // B cp.async issue (chunk i -> stage st)
    auto issueB = [&](int i, int st) {
        const u32* src = wB + i * (32 * BN);
        u32 dstb = sbase + (u32)((2 * ASZ + st * BSZ) * 4);
#pragma unroll
        for (int p = 0; p < BPT; p++) {
            int j = p * 256 + tid;                   // 16B chunk index
            int k = j / (BN / 4), c4 = j % (BN / 4);
            cp16(dstb + (u32)((k * SBP + c4 * 4) << 2), src + (k * BN + c4 * 4));
        }
        CP_COMMIT();
    };
    // A LDG into regs
    float rA[NLDA];
    auto ldgA = [&](int i) {
        const int koff = i >> 3, cic = i & 7;
        const int ky = koff / 3, kx = koff - ky * 3;
        const float* src = a_base + (size_t)(cic * 32) * PSZ + ky * PW + kx;
        const int strd = (CONV == 1) ? 2 : 1;
#pragma unroll
        for (int j = 0; j < NLDA; j++) rA[j] = __ldg(src + (size_t)(strd * j) * PSZ);
    };
    auto stsA = [&](int st) {
        u32* sp = dynsmem + st * ASZ + ak0 * SAP + apx;
        const int strd = (CONV == 1) ? 2 : 1;
#pragma unroll
        for (int j = 0; j < NLDA; j++) sp[strd * j * SAP] = __float_as_uint(rA[j]);
    };

    float acc[4][8][4];
#pragma unroll
    for (int mt = 0; mt < 4; mt++)
#pragma unroll
        for (int nt = 0; nt < 8; nt++)
#pragma unroll
            for (int q = 0; q < 4; q++) acc[mt][nt][q] = 0.0f;

    // ---- prologue ----
    issueB(0, 0);
    issueB(1, 1);
    ldgA(0); stsA(0);
    ldgA(1);
    CP_WAIT(1);
    __syncthreads();

    int stB = 0;
    for (int i = 0; i < 72; i++) {
        const int stA = i & 1;
        int stB2 = stB + 2; if (stB2 >= 3) stB2 -= 3;
        if (i + 2 < 72) issueB(i + 2, stB2);

        const u32* sA = dynsmem + stA * ASZ;
        const u32* sB = dynsmem + 2 * ASZ + stB * BSZ;
#pragma unroll
        for (int ks = 0; ks < 4; ks++) {
            const int kc = ks * 8 + lt;
            u32 a[4][4];
#pragma unroll
            for (int mt = 0; mt < 4; mt++) {
                const int b0 = kc * SAP + pxb + mt * 16 + lg;
                a[mt][0] = sA[b0];
                a[mt][1] = sA[b0 + 8];
                a[mt][2] = sA[b0 + 4 * SAP];
                a[mt][3] = sA[b0 + 4 * SAP + 8];
            }
            u32 b[8][2];
#pragma unroll
            for (int nt = 0; nt < 8; nt++) {
                const int bb = kc * SBP + cob + nt * 8 + lg;
                b[nt][0] = sB[bb];
                b[nt][1] = sB[bb + 4 * SBP];
            }
#pragma unroll
            for (int mt = 0; mt < 4; mt++)
#pragma unroll
                for (int nt = 0; nt < 8; nt++)
                    mma_tf32(acc[mt][nt], a[mt], b[nt]);
        }

        if (i + 1 < 72) {
            stsA(stA ^ 1);
            if (i + 2 < 72) { ldgA(i + 2); CP_WAIT(1); }
            else            { CP_WAIT(0); }
            __syncthreads();
        }
        if (++stB == 3) stB = 0;
    }

    // ---- epilogue ----
    if (CONV == 1) {
#pragma unroll
        for (int mt = 0; mt < 4; mt++) {
            const int p0 = pxb + mt * 16 + lg;
            const int p1 = p0 + 8;
            const int or0 = r0 + (p0 >> 6), oc0 = p0 & 63;
            const int or1 = r0 + (p1 >> 6), oc1 = p1 & 63;
#pragma unroll
            for (int nt = 0; nt < 8; nt++) {
                const int co = cob + nt * 8 + lt * 2;
                const float bv0 = bias[co], bv1 = bias[co + 1];
                float v00 = acc[mt][nt][0] + bv0;  v00 = (v00 >= 0.0f ? v00 : 0.2f * v00) * SQRT2F;
                float v01 = acc[mt][nt][1] + bv1;  v01 = (v01 >= 0.0f ? v01 : 0.2f * v01) * SQRT2F;
                float v10 = acc[mt][nt][2] + bv0;  v10 = (v10 >= 0.0f ? v10 : 0.2f * v10) * SQRT2F;
                float v11 = acc[mt][nt][3] + bv1;  v11 = (v11 >= 0.0f ? v11 : 0.2f * v11) * SQRT2F;
                g_out1[((size_t)(n * 256 + co)     << 12) + (or0 << 6) + oc0] = v00;
                g_out1[((size_t)(n * 256 + co + 1) << 12) + (or0 << 6) + oc0] = v01;
                g_out1[((size_t)(n * 256 + co)     << 12) + (or1 << 6) + oc1] = v10;
                g_out1[((size_t)(n * 256 + co + 1) << 12) + (or1 << 6) + oc1] = v11;
            }
        }
    } else {
        // fused: out = (conv2_act + bilinear_up(g_s64)) / sqrt(2); warp row u fixed.
        const int u = r0 + (wm >> 1);
        int rr0, rr1; float wr0, wr1;
        { int iu = u >> 1;
          if (u & 1) { rr0 = iu; rr1 = min(iu + 1, 63); wr0 = 0.75f; wr1 = 0.25f; }
          else       { rr0 = max(iu - 1, 0); rr1 = iu;  wr0 = 0.25f; wr1 = 0.75f; } }
#pragma unroll
        for (int mt = 0; mt < 4; mt++) {
#pragma unroll
            for (int half = 0; half < 2; half++) {
                const int px = pxb + mt * 16 + half * 8 + lg;
                const int v = px & 127;                       // output col
                int cc0, cc1; float wc0, wc1;
                { int jv = v >> 1;
                  if (v & 1) { cc0 = jv; cc1 = min(jv + 1, 63); wc0 = 0.75f; wc1 = 0.25f; }
                  else       { cc0 = max(jv - 1, 0); cc1 = jv;  wc0 = 0.25f; wc1 = 0.75f; } }
                const int i00 = (rr0 << 6) + cc0, i01 = (rr0 << 6) + cc1;
                const int i10 = (rr1 << 6) + cc0, i11 = (rr1 << 6) + cc1;
#pragma unroll
                for (int nt = 0; nt < 8; nt++) {
                    const int co = cob + nt * 8 + lt * 2;
                    const float bv0 = bias[co], bv1 = bias[co + 1];
                    float va = acc[mt][nt][half * 2 + 0] + bv0;
                    va = (va >= 0.0f ? va : 0.2f * va) * SQRT2F;
                    float vb = acc[mt][nt][half * 2 + 1] + bv1;
                    vb = (vb >= 0.0f ? vb : 0.2f * vb) * SQRT2F;
                    const float* s0 = g_s64 + ((size_t)(n * 128 + co) << 12);
                    const float* s1 = s0 + 4096;
                    float sk0 = wr0 * (wc0 * s0[i00] + wc1 * s0[i01])
                              + wr1 * (wc0 * s0[i10] + wc1 * s0[i11]);
                    float sk1 = wr0 * (wc0 * s1[i00] + wc1 * s1[i01])
                              + wr1 * (wc0 * s1[i10] + wc1 * s1[i11]);
                    dout[((size_t)(n * 128 + co)     << 14) + (u << 7) + v] = (va + sk0) * INVSQRT2F;
                    dout[((size_t)(n * 128 + co + 1) << 14) + (u << 7) + v] = (vb + sk1) * INVSQRT2F;
                }
            }
        }
    }
}

// ======================= bilinear 2x upsample (half-pixel, edge clamp) =================
__global__ void k_up256() {   // g_out1[.,.,64,64] -> g_up_pad interior [130x130], tf32-rounded
    int idx = blockIdx.x * 256 + threadIdx.x;
    int v = idx & 127, u = (idx >> 7) & 127, nc = idx >> 14;
    int i = u >> 1, j = v >> 1;
    int r0, r1, c0, c1; float wr0, wr1, wc0, wc1;
    if (u & 1) { r0 = i; r1 = min(i + 1, 63); wr0 = 0.75f; wr1 = 0.25f; }
    else       { r0 = max(i - 1, 0); r1 = i;  wr0 = 0.25f; wr1 = 0.75f; }
    if (v & 1) { c0 = j; c1 = min(j + 1, 63); wc0 = 0.75f; wc1 = 0.25f; }
    else       { c0 = max(j - 1, 0); c1 = j;  wc0 = 0.25f; wc1 = 0.75f; }
    const float* b = g_out1 + ((size_t)nc << 12);
    float val = wr0 * (wc0 * b[(r0 << 6) + c0] + wc1 * b[(r0 << 6) + c1])
              + wr1 * (wc0 * b[(r1 << 6) + c0] + wc1 * b[(r1 << 6) + c1]);
    g_up_pad[(size_t)nc * 16900 + (u + 1) * 130 + (v + 1)] = __uint_as_float(f2tf32(val));
}

// ======================= skip 1x1 conv at 64x64 (256->128), fp32 f32x2 =================
__global__ void __launch_bounds__(256) k_skip(const float* __restrict__ x) {
    const int n = blockIdx.z, cot = blockIdx.y;
    const int px0 = blockIdx.x * 64;
    const int tid = threadIdx.x;
    const int co_sub = tid >> 4, pxg = tid & 15;
    const int cobase = co_sub * 4, pxb = pxg * 4;
    __shared__ __align__(16) float s_x[16][64];
    __shared__ __align__(16) float s_w[16][64];
    ull acc[2][4];
#pragma unroll
    for (int p = 0; p < 2; p++)
#pragma unroll
        for (int j = 0; j < 4; j++) acc[p][j] = 0ull;

    for (int ci0 = 0; ci0 < 256; ci0 += 16) {
        __syncthreads();
        for (int i = tid; i < 1024; i += 256) {
            int ci_l = i >> 6, p = i & 63;
            s_x[ci_l][p] = x[((n * 256 + ci0 + ci_l) << 12) + px0 + p];
            s_w[ci_l][p] = g_wskT[(ci0 + ci_l) * 128 + cot * 64 + p];
        }
        __syncthreads();
#pragma unroll 4
        for (int ci = 0; ci < 16; ci++) {
            ull w0 = *(const ull*)&s_w[ci][cobase];
            ull w1 = *(const ull*)&s_w[ci][cobase + 2];
#pragma unroll
            for (int j = 0; j < 4; j++) {
                float v = s_x[ci][pxb + j];
                ull vb = pack2(v, v);
                fma2(acc[0][j], vb, w0);
                fma2(acc[1][j], vb, w1);
            }
        }
    }
#pragma unroll
    for (int p = 0; p < 2; p++) {
        int co = cot * 64 + cobase + 2 * p;
#pragma unroll
        for (int j = 0; j < 4; j++) {
            float lo, hi; unpack2(acc[p][j], lo, hi);
            g_s64[((n * 128 + co)     << 12) + px0 + pxb + j] = lo;
            g_s64[((n * 128 + co + 1) << 12) + px0 + pxb + j] = hi;
        }
    }
}

// ======================= launch =======================
extern "C" void kernel_launch(void* const* d_in, const int* in_sizes, int n_in,
                              void* d_out, int out_size) {
    const float* x   = (const float*)d_in[0];
    const float* w1  = (const float*)d_in[1];
    const float* b1  = (const float*)d_in[2];
    const float* w2  = (const float*)d_in[3];
    const float* b2  = (const float*)d_in[4];
    const float* wsk = (const float*)d_in[5];
    float* out = (float*)d_out;

    // conv1: A 2x(32*136) + B 3x(32*264); conv2: A 2x(32*264) + B 3x(32*136)
    const int SMEM1 = (2 * 32 * 136 + 3 * 32 * 264) * 4;   // 136192 B
    const int SMEM2 = (2 * 32 * 264 + 3 * 32 * 136) * 4;   // 119808 B
    cudaFuncSetAttribute(k_conv_mma<1>, cudaFuncAttributeMaxDynamicSharedMemorySize, SMEM1);
    cudaFuncSetAttribute(k_conv_mma<2>, cudaFuncAttributeMaxDynamicSharedMemorySize, SMEM2);

    k_wt1<<<2304, 256>>>(w1);
    k_wt2<<<1152, 256>>>(w2);
    k_wts<<<128, 256>>>(wsk);
    k_pad1<<<32768, 256>>>(x);

    k_conv_mma<1><<<dim3(32, 1, 8), 256, SMEM1>>>(b1, nullptr);
    k_up256<<<131072, 256>>>();                            // -> padded g_up_pad (tf32)
    k_skip<<<dim3(64, 2, 8), 256>>>(x);
    k_conv_mma<2><<<dim3(64, 1, 8), 256, SMEM2>>>(b2, out);  // conv2 + fused skip
}